// round 2
// baseline (speedup 1.0000x reference)
#include <cuda_runtime.h>
#include <cstdint>

// Problem constants (fixed by the dataset)
#define NTAB     8
#define BUCKETS  524288          // 2^19
#define BMASK    (BUCKETS - 1)
#define EMBED    64
#define T_LEN    4096
#define HIST     128             // max window
#define POS      64              // positions per block
#define THREADS  256

__device__ __constant__ unsigned int PRIMES[8] = {
    2654435761u, 2246822519u, 3266489917u, 2028178513u,
    1220703125u, 1610612741u, 805306457u,  402653189u
};

// Runtime dtype flag: 1 if tokens buffer is int32, 0 if int64.
__device__ int g_tok_is_i32;

// Probe: if tokens are little-endian int64 (values < 2^31), every odd int32
// word is a zero high-word. If they are genuine int32 tokens, 256 random
// values in [0,32000) are essentially never all zero. Deterministic per input.
__global__ void detect_dtype_kernel(const int* __restrict__ tok32)
{
    __shared__ int acc;
    if (threadIdx.x == 0) acc = 0;
    __syncthreads();
    // Inspect first 512 int32 words (safe: buffer is >= 128 KB either way).
    if (tok32[2 * threadIdx.x + 1] != 0) atomicOr(&acc, 1);
    __syncthreads();
    if (threadIdx.x == 0) g_tok_is_i32 = acc;
}

__global__ void __launch_bounds__(THREADS)
hash_tables_kernel(const void*   __restrict__ tokens_raw,
                   const float4* __restrict__ tables,   // [8, 524288, 64] fp32 as float4
                   float4*       __restrict__ out)      // [B, T, 512] fp32 as float4
{
    __shared__ int tok_s[HIST + POS];
    __shared__ int idx_s[POS * NTAB];

    const int blocks_per_row = T_LEN / POS;       // 64
    const int row = blockIdx.x / blocks_per_row;
    const int t0  = (blockIdx.x % blocks_per_row) * POS;

    const int is32 = g_tok_is_i32;
    const int*       tok32 = (const int*)tokens_raw;
    const long long* tok64 = (const long long*)tokens_raw;

    // ---- Phase 1: stage tokens (with 128-deep history, zero-padded) ----
    for (int i = threadIdx.x; i < HIST + POS; i += THREADS) {
        const int t = t0 - HIST + i;
        int v = 0;
        if (t >= 0) {
            const size_t k = (size_t)row * T_LEN + t;
            v = is32 ? tok32[k] : (int)tok64[k];
        }
        tok_s[i] = v;
    }
    __syncthreads();

    // ---- Phase 2: rolling xor-hash, snapshot at power-of-two windows ----
    if (threadIdx.x < POS) {
        const int tp = threadIdx.x;               // position p = t0 + tp
        unsigned long long h = 0ull;
        int w = 0;
        #pragma unroll
        for (int j = 0; j < 128; ++j) {
            // contribution of token at (p - (j+1)); zero-padded tokens give 0
            const unsigned int tok = (unsigned int)tok_s[HIST + tp - 1 - j];
            h ^= (unsigned long long)tok * PRIMES[j & 7];   // IMAD.WIDE.U32
            const int offset = j + 1;
            if (offset == 1 || offset == 2 || offset == 4 || offset == 8 ||
                offset == 16 || offset == 32 || offset == 64 || offset == 128) {
                // h is nonnegative (< 2^47), so % 2^19 == low-19-bit mask
                idx_s[tp * NTAB + w] = (int)((unsigned int)h & BMASK);
                ++w;
            }
        }
    }
    __syncthreads();

    // ---- Phase 3: gather 8 x 64 floats per position, coalesced float4 copy ----
    // k enumerates float4 units: k = pos*128 + tbl*16 + f4
    const int total = POS * NTAB * 16;            // 8192 float4 per block
    const size_t out_base = ((size_t)row * T_LEN + t0) << 7;  // float4 units
    #pragma unroll 8
    for (int k = threadIdx.x; k < total; k += THREADS) {
        const int pos = k >> 7;
        const int rem = k & 127;
        const int tbl = rem >> 4;
        const int f4  = rem & 15;
        const int bucket = idx_s[pos * NTAB + tbl];
        const float4 v = tables[(((size_t)tbl * BUCKETS + (size_t)bucket) << 4) + f4];
        out[out_base + ((size_t)pos << 7) + rem] = v;
    }
}

extern "C" void kernel_launch(void* const* d_in, const int* in_sizes, int n_in,
                              void* d_out, int out_size)
{
    const void*   tokens = d_in[0];               // int64 OR int32 (B, T) — probed
    const float4* tables = (const float4*)d_in[1];// fp32 (8, 524288, 64)
    float4*       out    = (float4*)d_out;        // fp32 (B, T, 512)

    const int rows = in_sizes[0] / T_LEN;         // B = 8
    const int grid = rows * (T_LEN / POS);        // 512 blocks

    detect_dtype_kernel<<<1, 256>>>((const int*)tokens);
    hash_tables_kernel<<<grid, THREADS>>>(tokens, tables, out);
}